// round 2
// baseline (speedup 1.0000x reference)
#include <cuda_runtime.h>

// Problem constants
#define B_  32
#define M_  8192
#define Q_  64
#define D_  128

#define S_CHUNKS 16
#define CHUNK    (M_ / S_CHUNKS)   // 512 m per block
#define MT       128               // m-tile
#define NTILES   (CHUNK / MT)      // 4
#define THREADS  256

// Shared memory layout (floats)
//  a_s   : 128*128      = 16384   (story_a tile, then reused for story_c tile)
//  u_s   : 64*128       = 8192    (u, XOR-swizzled granules)
//  s_buf : 128*65       = 8320    (scores, padded rows, conflict-free softmax)
//  p_s   : 64*128       = 8192    (softmaxed p, transposed+swizzled)
#define A_OFF   0
#define U_OFF   16384
#define S_OFF   (16384 + 8192)
#define P_OFF   (16384 + 8192 + 8320)
#define SMEM_FLOATS (16384 + 8192 + 8320 + 8192)
#define SMEM_BYTES  (SMEM_FLOATS * 4)

// ---------------------------------------------------------------------------
// Kernel A: out[b,q,:] = u[b,q,:] @ H   (initializes the whole output)
// ---------------------------------------------------------------------------
__global__ __launch_bounds__(128) void uh_kernel(
    const float* __restrict__ u, const float* __restrict__ H,
    float* __restrict__ out)
{
    __shared__ float us[D_];
    int bq  = blockIdx.x;        // 0 .. B*Q-1
    int tid = threadIdx.x;       // d index
    us[tid] = u[(size_t)bq * D_ + tid];
    __syncthreads();
    float acc = 0.f;
#pragma unroll 16
    for (int e = 0; e < D_; ++e)
        acc += us[e] * H[e * D_ + tid];
    out[(size_t)bq * D_ + tid] = acc;
}

// ---------------------------------------------------------------------------
// Kernel B: fused  scores -> softmax(axis=Q) -> p^T @ story_c, atomicAdd out
// ---------------------------------------------------------------------------
__global__ __launch_bounds__(THREADS, 1) void attn_kernel(
    const float* __restrict__ story_a, const float* __restrict__ u,
    const float* __restrict__ story_c, float* __restrict__ out)
{
    extern __shared__ float sm[];
    float*  a_s   = sm + A_OFF;
    float*  u_s   = sm + U_OFF;
    float*  s_buf = sm + S_OFF;
    float*  p_s   = sm + P_OFF;
    float4* a_s4  = reinterpret_cast<float4*>(a_s);
    float4* u_s4  = reinterpret_cast<float4*>(u_s);
    float4* p_s4  = reinterpret_cast<float4*>(p_s);

    const int tid   = threadIdx.x;
    const int b     = blockIdx.y;
    const int chunk = blockIdx.x;
    const int m_base = chunk * CHUNK;

    // ---- load u (64 x 128) into smem with XOR-swizzled 16B granules ----
    {
        const float4* ug4 = reinterpret_cast<const float4*>(u + (size_t)b * Q_ * D_);
        for (int gi = tid; gi < Q_ * D_ / 4; gi += THREADS) {
            int q  = gi >> 5;          // row (32 granules per row)
            int k4 = gi & 31;          // granule within row
            int g  = k4 ^ ((q >> 2) & 7);
            u_s4[q * 32 + g] = ug4[gi];
        }
    }

    // GEMM1 thread map: 8m x 4q per thread
    const int tq = tid & 15;   // q-group (16)
    const int tm = tid >> 4;   // m-group (16)
    // GEMM2 thread map: 4q x 8d per thread
    const int dg = tid & 15;   // d-group (16)
    const int qg = tid >> 4;   // q-group (16)

    // persistent output accumulators: c[4q][8d]
    float c[4][8];
#pragma unroll
    for (int j = 0; j < 4; ++j)
#pragma unroll
        for (int dd = 0; dd < 8; ++dd) c[j][dd] = 0.f;

    for (int t = 0; t < NTILES; ++t) {
        const int m0 = m_base + t * MT;

        __syncthreads();   // previous GEMM2 done with a_s / this covers u_s too
        // ---- stage story_a tile (128 x 128), natural layout ----
        {
            const float4* ag4 = reinterpret_cast<const float4*>(
                story_a + ((size_t)b * M_ + m0) * D_);
            for (int gi = tid; gi < MT * D_ / 4; gi += THREADS)
                a_s4[gi] = ag4[gi];
        }
        __syncthreads();

        // ---- GEMM1: s[m][q] = sum_d a[m][d] * u[q][d] ----
        float s[8][4];
#pragma unroll
        for (int i = 0; i < 8; ++i)
#pragma unroll
            for (int j = 0; j < 4; ++j) s[i][j] = 0.f;

#pragma unroll 4
        for (int k4 = 0; k4 < 32; ++k4) {
            float4 uv[4];
#pragma unroll
            for (int j = 0; j < 4; ++j) {
                int q = tq * 4 + j;
                uv[j] = u_s4[q * 32 + (k4 ^ (tq & 7))];
            }
#pragma unroll
            for (int i = 0; i < 8; ++i) {
                float4 av = a_s4[(tm * 8 + i) * 32 + k4];
#pragma unroll
                for (int j = 0; j < 4; ++j) {
                    s[i][j] += av.x * uv[j].x;
                    s[i][j] += av.y * uv[j].y;
                    s[i][j] += av.z * uv[j].z;
                    s[i][j] += av.w * uv[j].w;
                }
            }
        }

        // ---- spill scores to smem (row len 65 -> conflict-free softmax) ----
#pragma unroll
        for (int i = 0; i < 8; ++i)
#pragma unroll
            for (int j = 0; j < 4; ++j)
                s_buf[(tm * 8 + i) * 65 + tq * 4 + j] = s[i][j];
        __syncthreads();

        // ---- softmax over Q per m-row; write p transposed+swizzled ----
        if (tid < MT) {
            float* row = s_buf + tid * 65;
            float mx = -1e30f;
#pragma unroll 8
            for (int q = 0; q < Q_; ++q) mx = fmaxf(mx, row[q]);
            float sum = 0.f;
#pragma unroll 8
            for (int q = 0; q < Q_; ++q) {
                float ex = __expf(row[q] - mx);
                sum += ex;
                row[q] = ex;
            }
            float inv = 1.f / sum;
            const int mloc = tid;
            const int mg   = mloc >> 2;
            const int mr   = mloc & 3;
#pragma unroll 8
            for (int q = 0; q < Q_; ++q) {
                int gc = mg ^ ((q >> 2) & 15);
                p_s[q * 128 + gc * 4 + mr] = row[q] * inv;
            }
        }
        __syncthreads();

        // ---- stage story_c tile over a_s ----
        {
            const float4* cg4 = reinterpret_cast<const float4*>(
                story_c + ((size_t)b * M_ + m0) * D_);
            for (int gi = tid; gi < MT * D_ / 4; gi += THREADS)
                a_s4[gi] = cg4[gi];
        }
        __syncthreads();

        // ---- GEMM2: c[q][d] += sum_m p[q][m] * sc[m][d] ----
#pragma unroll 4
        for (int k4 = 0; k4 < 32; ++k4) {
            float pj[4][4];
#pragma unroll
            for (int j = 0; j < 4; ++j) {
                int q = qg * 4 + j;
                float4 pv = p_s4[q * 32 + (k4 ^ (qg & 15))];
                pj[j][0] = pv.x; pj[j][1] = pv.y; pj[j][2] = pv.z; pj[j][3] = pv.w;
            }
#pragma unroll
            for (int kk = 0; kk < 4; ++kk) {
                int m = k4 * 4 + kk;
                float4 c0 = a_s4[m * 32 + dg * 2 + 0];
                float4 c1 = a_s4[m * 32 + dg * 2 + 1];
#pragma unroll
                for (int j = 0; j < 4; ++j) {
                    float p = pj[j][kk];
                    c[j][0] += p * c0.x; c[j][1] += p * c0.y;
                    c[j][2] += p * c0.z; c[j][3] += p * c0.w;
                    c[j][4] += p * c1.x; c[j][5] += p * c1.y;
                    c[j][6] += p * c1.z; c[j][7] += p * c1.w;
                }
            }
        }
    }

    // ---- accumulate partial c into global out ----
#pragma unroll
    for (int j = 0; j < 4; ++j) {
        int q = qg * 4 + j;
        float* orow = out + ((size_t)b * Q_ + q) * D_ + dg * 8;
#pragma unroll
        for (int dd = 0; dd < 8; ++dd)
            atomicAdd(orow + dd, c[j][dd]);
    }
}

// ---------------------------------------------------------------------------
extern "C" void kernel_launch(void* const* d_in, const int* in_sizes, int n_in,
                              void* d_out, int out_size)
{
    (void)in_sizes; (void)n_in; (void)out_size;
    const float* story_a = (const float*)d_in[0];
    const float* u       = (const float*)d_in[1];
    const float* story_c = (const float*)d_in[2];
    const float* H       = (const float*)d_in[3];
    float* out = (float*)d_out;

    // 1) out = u @ H (initializes every output element)
    uh_kernel<<<B_ * Q_, 128>>>(u, H, out);

    // 2) fused attention accumulate
    cudaFuncSetAttribute(attn_kernel,
                         cudaFuncAttributeMaxDynamicSharedMemorySize, SMEM_BYTES);
    dim3 grid(S_CHUNKS, B_);
    attn_kernel<<<grid, THREADS, SMEM_BYTES>>>(story_a, u, story_c, out);
}

// round 3
// speedup vs baseline: 1.0011x; 1.0011x over previous
#include <cuda_runtime.h>

// Problem constants
#define B_  32
#define M_  8192
#define Q_  64
#define D_  128

#define S_CHUNKS 16
#define CHUNK    (M_ / S_CHUNKS)   // 512 m per block
#define MT       128               // m-tile
#define NTILES   (CHUNK / MT)      // 4
#define THREADS  256

// Shared memory layout (floats)
//  a_s   : 128*128      = 16384   (story_a tile, then reused for story_c tile)
//  u_s   : 64*128       = 8192    (u, XOR-swizzled granules)
//  s_buf : 128*65       = 8320    (scores, padded rows, conflict-free softmax)
//  p_s   : 64*128       = 8192    (softmaxed p, transposed+swizzled)
#define A_OFF   0
#define U_OFF   16384
#define S_OFF   (16384 + 8192)
#define P_OFF   (16384 + 8192 + 8320)
#define SMEM_FLOATS (16384 + 8192 + 8320 + 8192)
#define SMEM_BYTES  (SMEM_FLOATS * 4)

// ---------------------------------------------------------------------------
// Kernel A: out[b,q,:] = u[b,q,:] @ H   (initializes the whole output)
// ---------------------------------------------------------------------------
__global__ __launch_bounds__(128) void uh_kernel(
    const float* __restrict__ u, const float* __restrict__ H,
    float* __restrict__ out)
{
    __shared__ float us[D_];
    int bq  = blockIdx.x;        // 0 .. B*Q-1
    int tid = threadIdx.x;       // d index
    us[tid] = u[(size_t)bq * D_ + tid];
    __syncthreads();
    float acc = 0.f;
#pragma unroll 16
    for (int e = 0; e < D_; ++e)
        acc += us[e] * H[e * D_ + tid];
    out[(size_t)bq * D_ + tid] = acc;
}

// ---------------------------------------------------------------------------
// Kernel B: fused  scores -> softmax(axis=Q) -> p^T @ story_c, atomicAdd out
// ---------------------------------------------------------------------------
__global__ __launch_bounds__(THREADS, 1) void attn_kernel(
    const float* __restrict__ story_a, const float* __restrict__ u,
    const float* __restrict__ story_c, float* __restrict__ out)
{
    extern __shared__ float sm[];
    float*  a_s   = sm + A_OFF;
    float*  u_s   = sm + U_OFF;
    float*  s_buf = sm + S_OFF;
    float*  p_s   = sm + P_OFF;
    float4* a_s4  = reinterpret_cast<float4*>(a_s);
    float4* u_s4  = reinterpret_cast<float4*>(u_s);
    float4* p_s4  = reinterpret_cast<float4*>(p_s);

    const int tid   = threadIdx.x;
    const int b     = blockIdx.y;
    const int chunk = blockIdx.x;
    const int m_base = chunk * CHUNK;

    // ---- load u (64 x 128) into smem with XOR-swizzled 16B granules ----
    {
        const float4* ug4 = reinterpret_cast<const float4*>(u + (size_t)b * Q_ * D_);
        for (int gi = tid; gi < Q_ * D_ / 4; gi += THREADS) {
            int q  = gi >> 5;          // row (32 granules per row)
            int k4 = gi & 31;          // granule within row
            int g  = k4 ^ ((q >> 2) & 7);
            u_s4[q * 32 + g] = ug4[gi];
        }
    }

    // GEMM1 thread map: 8m x 4q per thread
    const int tq = tid & 15;   // q-group (16)
    const int tm = tid >> 4;   // m-group (16)
    // GEMM2 thread map: 4q x 8d per thread
    const int dg = tid & 15;   // d-group (16)
    const int qg = tid >> 4;   // q-group (16)

    // persistent output accumulators: c[4q][8d]
    float c[4][8];
#pragma unroll
    for (int j = 0; j < 4; ++j)
#pragma unroll
        for (int dd = 0; dd < 8; ++dd) c[j][dd] = 0.f;

    for (int t = 0; t < NTILES; ++t) {
        const int m0 = m_base + t * MT;

        __syncthreads();   // previous GEMM2 done with a_s / this covers u_s too
        // ---- stage story_a tile (128 x 128), natural layout ----
        {
            const float4* ag4 = reinterpret_cast<const float4*>(
                story_a + ((size_t)b * M_ + m0) * D_);
            for (int gi = tid; gi < MT * D_ / 4; gi += THREADS)
                a_s4[gi] = ag4[gi];
        }
        __syncthreads();

        // ---- GEMM1: s[m][q] = sum_d a[m][d] * u[q][d] ----
        float s[8][4];
#pragma unroll
        for (int i = 0; i < 8; ++i)
#pragma unroll
            for (int j = 0; j < 4; ++j) s[i][j] = 0.f;

#pragma unroll 4
        for (int k4 = 0; k4 < 32; ++k4) {
            float4 uv[4];
#pragma unroll
            for (int j = 0; j < 4; ++j) {
                int q = tq * 4 + j;
                uv[j] = u_s4[q * 32 + (k4 ^ (tq & 7))];
            }
#pragma unroll
            for (int i = 0; i < 8; ++i) {
                float4 av = a_s4[(tm * 8 + i) * 32 + k4];
#pragma unroll
                for (int j = 0; j < 4; ++j) {
                    s[i][j] += av.x * uv[j].x;
                    s[i][j] += av.y * uv[j].y;
                    s[i][j] += av.z * uv[j].z;
                    s[i][j] += av.w * uv[j].w;
                }
            }
        }

        // ---- spill scores to smem (row len 65 -> conflict-free softmax) ----
#pragma unroll
        for (int i = 0; i < 8; ++i)
#pragma unroll
            for (int j = 0; j < 4; ++j)
                s_buf[(tm * 8 + i) * 65 + tq * 4 + j] = s[i][j];
        __syncthreads();

        // ---- softmax over Q per m-row; write p transposed+swizzled ----
        if (tid < MT) {
            float* row = s_buf + tid * 65;
            float mx = -1e30f;
#pragma unroll 8
            for (int q = 0; q < Q_; ++q) mx = fmaxf(mx, row[q]);
            float sum = 0.f;
#pragma unroll 8
            for (int q = 0; q < Q_; ++q) {
                float ex = __expf(row[q] - mx);
                sum += ex;
                row[q] = ex;
            }
            float inv = 1.f / sum;
            const int mloc = tid;
            const int mg   = mloc >> 2;
            const int mr   = mloc & 3;
#pragma unroll 8
            for (int q = 0; q < Q_; ++q) {
                int gc = mg ^ ((q >> 2) & 15);
                p_s[q * 128 + gc * 4 + mr] = row[q] * inv;
            }
        }
        __syncthreads();

        // ---- stage story_c tile over a_s ----
        {
            const float4* cg4 = reinterpret_cast<const float4*>(
                story_c + ((size_t)b * M_ + m0) * D_);
            for (int gi = tid; gi < MT * D_ / 4; gi += THREADS)
                a_s4[gi] = cg4[gi];
        }
        __syncthreads();

        // ---- GEMM2: c[q][d] += sum_m p[q][m] * sc[m][d] ----
#pragma unroll 4
        for (int k4 = 0; k4 < 32; ++k4) {
            float pj[4][4];
#pragma unroll
            for (int j = 0; j < 4; ++j) {
                int q = qg * 4 + j;
                float4 pv = p_s4[q * 32 + (k4 ^ (qg & 15))];
                pj[j][0] = pv.x; pj[j][1] = pv.y; pj[j][2] = pv.z; pj[j][3] = pv.w;
            }
#pragma unroll
            for (int kk = 0; kk < 4; ++kk) {
                int m = k4 * 4 + kk;
                float4 c0 = a_s4[m * 32 + dg * 2 + 0];
                float4 c1 = a_s4[m * 32 + dg * 2 + 1];
#pragma unroll
                for (int j = 0; j < 4; ++j) {
                    float p = pj[j][kk];
                    c[j][0] += p * c0.x; c[j][1] += p * c0.y;
                    c[j][2] += p * c0.z; c[j][3] += p * c0.w;
                    c[j][4] += p * c1.x; c[j][5] += p * c1.y;
                    c[j][6] += p * c1.z; c[j][7] += p * c1.w;
                }
            }
        }
    }

    // ---- accumulate partial c into global out ----
#pragma unroll
    for (int j = 0; j < 4; ++j) {
        int q = qg * 4 + j;
        float* orow = out + ((size_t)b * Q_ + q) * D_ + dg * 8;
#pragma unroll
        for (int dd = 0; dd < 8; ++dd)
            atomicAdd(orow + dd, c[j][dd]);
    }
}

// ---------------------------------------------------------------------------
extern "C" void kernel_launch(void* const* d_in, const int* in_sizes, int n_in,
                              void* d_out, int out_size)
{
    (void)in_sizes; (void)n_in; (void)out_size;
    const float* story_a = (const float*)d_in[0];
    const float* u       = (const float*)d_in[1];
    const float* story_c = (const float*)d_in[2];
    const float* H       = (const float*)d_in[3];
    float* out = (float*)d_out;

    // 1) out = u @ H (initializes every output element)
    uh_kernel<<<B_ * Q_, 128>>>(u, H, out);

    // 2) fused attention accumulate
    cudaFuncSetAttribute(attn_kernel,
                         cudaFuncAttributeMaxDynamicSharedMemorySize, SMEM_BYTES);
    dim3 grid(S_CHUNKS, B_);
    attn_kernel<<<grid, THREADS, SMEM_BYTES>>>(story_a, u, story_c, out);
}

// round 5
// speedup vs baseline: 2.1582x; 2.1558x over previous
#include <cuda_runtime.h>
#include <cuda_bf16.h>
#include <cstdint>

#define B_ 32
#define M_ 8192
#define QN 64
#define DN 128
#define S_CHUNKS 16
#define CHUNK 512
#define MT 128
#define NT 4
#define THREADS 256

#define ROWB  272   // A/C/U tile row stride (128 bf16 = 256B + 16B pad)
#define PROWB 144   // P tile row stride (64 bf16 = 128B + 16B pad)

// shared memory byte offsets
#define A_HI 0
#define A_LO (A_HI + MT * ROWB)
#define C_HI (A_LO + MT * ROWB)
#define C_LO (C_HI + MT * ROWB)
#define U_HI (C_LO + MT * ROWB)
#define U_LO (U_HI + QN * ROWB)
#define P_HI (U_LO + QN * ROWB)
#define P_LO (P_HI + MT * PROWB)
#define SMEM_TOTAL (P_LO + MT * PROWB)   // 210,944 bytes

// 16 MB partial-sum scratch: [b*16+chunk][q*128+d]
__device__ float g_part[(size_t)B_ * S_CHUNKS * QN * DN];

__device__ __forceinline__ uint32_t smem_u32(const void* p) {
    uint32_t a;
    asm("{ .reg .u64 t; cvta.to.shared.u64 t, %1; cvt.u32.u64 %0, t; }" : "=r"(a) : "l"(p));
    return a;
}
__device__ __forceinline__ void ldsm4(uint32_t* r, uint32_t a) {
    asm volatile("ldmatrix.sync.aligned.m8n8.x4.shared.b16 {%0,%1,%2,%3}, [%4];"
                 : "=r"(r[0]), "=r"(r[1]), "=r"(r[2]), "=r"(r[3]) : "r"(a));
}
__device__ __forceinline__ void ldsm4t(uint32_t* r, uint32_t a) {
    asm volatile("ldmatrix.sync.aligned.m8n8.x4.trans.shared.b16 {%0,%1,%2,%3}, [%4];"
                 : "=r"(r[0]), "=r"(r[1]), "=r"(r[2]), "=r"(r[3]) : "r"(a));
}
__device__ __forceinline__ void mma_bf16(float* d, const uint32_t* a, const uint32_t* b) {
    asm volatile(
        "mma.sync.aligned.m16n8k16.row.col.f32.bf16.bf16.f32 "
        "{%0,%1,%2,%3}, {%4,%5,%6,%7}, {%8,%9}, {%0,%1,%2,%3};"
        : "+f"(d[0]), "+f"(d[1]), "+f"(d[2]), "+f"(d[3])
        : "r"(a[0]), "r"(a[1]), "r"(a[2]), "r"(a[3]), "r"(b[0]), "r"(b[1]));
}
// split two floats into packed bf16 hi pair + bf16 lo (residual) pair
__device__ __forceinline__ void cvt2(float x0, float x1, uint32_t& hi, uint32_t& lo) {
    __nv_bfloat162 h = __float22bfloat162_rn(make_float2(x0, x1));
    hi = *reinterpret_cast<uint32_t*>(&h);
    float h0 = __uint_as_float(hi << 16);
    float h1 = __uint_as_float(hi & 0xFFFF0000u);
    __nv_bfloat162 l = __float22bfloat162_rn(make_float2(x0 - h0, x1 - h1));
    lo = *reinterpret_cast<uint32_t*>(&l);
}

// ---------------------------------------------------------------------------
__global__ __launch_bounds__(128) void uh_kernel(
    const float* __restrict__ u, const float* __restrict__ H, float* __restrict__ out)
{
    __shared__ float us[DN];
    int bq = blockIdx.x, tid = threadIdx.x;
    us[tid] = u[(size_t)bq * DN + tid];
    __syncthreads();
    float acc = 0.f;
#pragma unroll 16
    for (int e = 0; e < DN; ++e) acc += us[e] * H[e * DN + tid];
    out[(size_t)bq * DN + tid] = acc;
}

// ---------------------------------------------------------------------------
__global__ __launch_bounds__(THREADS, 1) void attn_mma(
    const float* __restrict__ story_a, const float* __restrict__ u,
    const float* __restrict__ story_c)
{
    extern __shared__ char sm[];
    const uint32_t sb = smem_u32(sm);
    const int tid = threadIdx.x, lane = tid & 31, wid = tid >> 5;
    const int b = blockIdx.y, chunk = blockIdx.x;
    const int m_base_g = chunk * CHUNK;

    // ---- stage u (hi/lo), [q][d] rows of ROWB ----
    {
        const float4* g4 = reinterpret_cast<const float4*>(u + (size_t)b * QN * DN);
        for (int i = tid; i < QN * DN / 4; i += THREADS) {
            int q = i >> 5, d4 = (i & 31) << 2;
            float4 v = g4[i];
            uint32_t h0, l0, h1, l1;
            cvt2(v.x, v.y, h0, l0); cvt2(v.z, v.w, h1, l1);
            uint32_t off = q * ROWB + d4 * 2;
            *reinterpret_cast<uint2*>(sm + U_HI + off) = make_uint2(h0, h1);
            *reinterpret_cast<uint2*>(sm + U_LO + off) = make_uint2(l0, l1);
        }
    }

    // GEMM1 mapping: warp = 16m x 64q
    const int g1_m = wid * 16;
    const uint32_t a1_row = (uint32_t)(g1_m + (lane & 15));          // A row
    const uint32_t a1_kh  = (lane & 16) ? 16u : 0u;                  // +8 k elems (bytes)
    const uint32_t b1_rowoff = (uint32_t)((lane & 7) + ((lane & 16) ? 8 : 0));
    const uint32_t b1_kh  = (lane & 8) ? 16u : 0u;

    // GEMM2 mapping: warp = 16q x 64d
    const int g2_q = (wid & 3) * 16;
    const int g2_d = (wid >> 2) * 64;
    const uint32_t pa_rowoff = (uint32_t)((lane & 7) + ((lane & 16) ? 8 : 0));
    const uint32_t pa_qoff   = (uint32_t)((g2_q + ((lane & 8) ? 8 : 0)) * 2);
    const uint32_t cb_rowoff = (uint32_t)((lane & 7) + ((lane & 8) ? 8 : 0));
    const uint32_t cb_nh     = (lane & 16) ? 16u : 0u;

    float cacc[8][4];
#pragma unroll
    for (int i = 0; i < 8; ++i)
#pragma unroll
        for (int j = 0; j < 4; ++j) cacc[i][j] = 0.f;

    for (int t = 0; t < NT; ++t) {
        __syncthreads();   // previous tile's GEMM2 done with C/P

        // ---- stage story_a & story_c tiles (hi/lo), [m][d] ----
        {
            const float4* ga = reinterpret_cast<const float4*>(
                story_a + ((size_t)b * M_ + m_base_g + t * MT) * DN);
            const float4* gc = reinterpret_cast<const float4*>(
                story_c + ((size_t)b * M_ + m_base_g + t * MT) * DN);
            for (int i = tid; i < MT * DN / 4; i += THREADS) {
                int m = i >> 5, d4 = (i & 31) << 2;
                uint32_t off = m * ROWB + d4 * 2;
                float4 v = ga[i];
                uint32_t h0, l0, h1, l1;
                cvt2(v.x, v.y, h0, l0); cvt2(v.z, v.w, h1, l1);
                *reinterpret_cast<uint2*>(sm + A_HI + off) = make_uint2(h0, h1);
                *reinterpret_cast<uint2*>(sm + A_LO + off) = make_uint2(l0, l1);
                v = gc[i];
                cvt2(v.x, v.y, h0, l0); cvt2(v.z, v.w, h1, l1);
                *reinterpret_cast<uint2*>(sm + C_HI + off) = make_uint2(h0, h1);
                *reinterpret_cast<uint2*>(sm + C_LO + off) = make_uint2(l0, l1);
            }
        }
        __syncthreads();

        // ---- GEMM1: S[16m][64q], 3-pass hi/lo ----
        float s[8][4];
#pragma unroll
        for (int i = 0; i < 8; ++i)
#pragma unroll
            for (int j = 0; j < 4; ++j) s[i][j] = 0.f;

#pragma unroll
        for (int ks = 0; ks < 8; ++ks) {
            uint32_t ah[4], al[4];
            uint32_t aaddr = sb + A_HI + a1_row * ROWB + (uint32_t)ks * 32 + a1_kh;
            ldsm4(ah, aaddr);
            ldsm4(al, aaddr + (A_LO - A_HI));
#pragma unroll
            for (int ntp = 0; ntp < 4; ++ntp) {
                uint32_t bh[4], bl[4];
                uint32_t baddr = sb + U_HI + (ntp * 16 + b1_rowoff) * ROWB
                               + (uint32_t)ks * 32 + b1_kh;
                ldsm4(bh, baddr);
                ldsm4(bl, baddr + (U_LO - U_HI));
#pragma unroll
                for (int j = 0; j < 2; ++j) {
                    mma_bf16(s[ntp * 2 + j], ah, bh + 2 * j);
                    mma_bf16(s[ntp * 2 + j], ah, bl + 2 * j);
                    mma_bf16(s[ntp * 2 + j], al, bh + 2 * j);
                }
            }
        }

        // ---- softmax over q, warp-local (rows r1, r2 = r1+8) ----
        {
            float mx1 = -1e30f, mx2 = -1e30f;
#pragma unroll
            for (int nt = 0; nt < 8; ++nt) {
                mx1 = fmaxf(mx1, fmaxf(s[nt][0], s[nt][1]));
                mx2 = fmaxf(mx2, fmaxf(s[nt][2], s[nt][3]));
            }
            mx1 = fmaxf(mx1, __shfl_xor_sync(0xffffffffu, mx1, 1));
            mx1 = fmaxf(mx1, __shfl_xor_sync(0xffffffffu, mx1, 2));
            mx2 = fmaxf(mx2, __shfl_xor_sync(0xffffffffu, mx2, 1));
            mx2 = fmaxf(mx2, __shfl_xor_sync(0xffffffffu, mx2, 2));
            float sum1 = 0.f, sum2 = 0.f;
#pragma unroll
            for (int nt = 0; nt < 8; ++nt) {
                s[nt][0] = __expf(s[nt][0] - mx1); sum1 += s[nt][0];
                s[nt][1] = __expf(s[nt][1] - mx1); sum1 += s[nt][1];
                s[nt][2] = __expf(s[nt][2] - mx2); sum2 += s[nt][2];
                s[nt][3] = __expf(s[nt][3] - mx2); sum2 += s[nt][3];
            }
            sum1 += __shfl_xor_sync(0xffffffffu, sum1, 1);
            sum1 += __shfl_xor_sync(0xffffffffu, sum1, 2);
            sum2 += __shfl_xor_sync(0xffffffffu, sum2, 1);
            sum2 += __shfl_xor_sync(0xffffffffu, sum2, 2);
            float inv1 = 1.f / sum1, inv2 = 1.f / sum2;

            const int r1 = g1_m + (lane >> 2), r2 = r1 + 8;
            const uint32_t qb = (uint32_t)((lane & 3) * 2) * 2;  // byte offset of q pair
#pragma unroll
            for (int nt = 0; nt < 8; ++nt) {
                uint32_t h, l;
                uint32_t off = (uint32_t)nt * 16 + qb;
                cvt2(s[nt][0] * inv1, s[nt][1] * inv1, h, l);
                *reinterpret_cast<uint32_t*>(sm + P_HI + r1 * PROWB + off) = h;
                *reinterpret_cast<uint32_t*>(sm + P_LO + r1 * PROWB + off) = l;
                cvt2(s[nt][2] * inv2, s[nt][3] * inv2, h, l);
                *reinterpret_cast<uint32_t*>(sm + P_HI + r2 * PROWB + off) = h;
                *reinterpret_cast<uint32_t*>(sm + P_LO + r2 * PROWB + off) = l;
            }
        }
        __syncthreads();

        // ---- GEMM2: C[16q][64d] += P^T * SC, 3-pass hi/lo ----
#pragma unroll
        for (int ks = 0; ks < 8; ++ks) {
            uint32_t ph[4], pl[4];
            uint32_t paddr = sb + P_HI + ((uint32_t)ks * 16 + pa_rowoff) * PROWB + pa_qoff;
            ldsm4t(ph, paddr);
            ldsm4t(pl, paddr + (P_LO - P_HI));
#pragma unroll
            for (int ntp = 0; ntp < 4; ++ntp) {
                uint32_t bh[4], bl[4];
                uint32_t baddr = sb + C_HI + ((uint32_t)ks * 16 + cb_rowoff) * ROWB
                               + (uint32_t)(g2_d + ntp * 16) * 2 + cb_nh;
                ldsm4t(bh, baddr);
                ldsm4t(bl, baddr + (C_LO - C_HI));
#pragma unroll
                for (int j = 0; j < 2; ++j) {
                    mma_bf16(cacc[ntp * 2 + j], ph, bh + 2 * j);
                    mma_bf16(cacc[ntp * 2 + j], ph, bl + 2 * j);
                    mma_bf16(cacc[ntp * 2 + j], pl, bh + 2 * j);
                }
            }
        }
    }

    // ---- write partials to scratch ----
    {
        float* part = g_part + (size_t)(b * S_CHUNKS + chunk) * (QN * DN);
        const int q1 = g2_q + (lane >> 2), q2 = q1 + 8;
#pragma unroll
        for (int nt = 0; nt < 8; ++nt) {
            int d0 = g2_d + nt * 8 + (lane & 3) * 2;
            *reinterpret_cast<float2*>(part + q1 * DN + d0) =
                make_float2(cacc[nt][0], cacc[nt][1]);
            *reinterpret_cast<float2*>(part + q2 * DN + d0) =
                make_float2(cacc[nt][2], cacc[nt][3]);
        }
    }
}

// ---------------------------------------------------------------------------
__global__ __launch_bounds__(256) void reduce_kernel(float* __restrict__ out)
{
    int i = blockIdx.x * 256 + threadIdx.x;       // 0 .. B*Q*D-1
    int b = i >> 13;                              // Q*D = 8192
    int qd = i & 8191;
    float v = 0.f;
#pragma unroll
    for (int ch = 0; ch < S_CHUNKS; ++ch)
        v += g_part[(size_t)(b * S_CHUNKS + ch) * (QN * DN) + qd];
    out[i] += v;
}

// ---------------------------------------------------------------------------
extern "C" void kernel_launch(void* const* d_in, const int* in_sizes, int n_in,
                              void* d_out, int out_size)
{
    (void)in_sizes; (void)n_in; (void)out_size;
    const float* story_a = (const float*)d_in[0];
    const float* u       = (const float*)d_in[1];
    const float* story_c = (const float*)d_in[2];
    const float* H       = (const float*)d_in[3];
    float* out = (float*)d_out;

    uh_kernel<<<B_ * QN, 128>>>(u, H, out);

    cudaFuncSetAttribute(attn_mma, cudaFuncAttributeMaxDynamicSharedMemorySize, SMEM_TOTAL);
    dim3 grid(S_CHUNKS, B_);
    attn_mma<<<grid, THREADS, SMEM_TOTAL>>>(story_a, u, story_c);

    reduce_kernel<<<(B_ * QN * DN) / 256, 256>>>(out);
}

// round 6
// speedup vs baseline: 2.2454x; 1.0404x over previous
#include <cuda_runtime.h>
#include <cuda_bf16.h>
#include <cstdint>

#define B_ 32
#define M_ 8192
#define QN 64
#define DN 128
#define S_CHUNKS 32
#define CHUNK 256
#define MT 64
#define NT 4
#define THREADS 128

#define ROW  256   // A/C/U row bytes (128 bf16), XOR-swizzled granules
#define PROW 128   // P row bytes (64 bf16)

// shared memory byte offsets (112KB total -> 2 CTAs/SM)
#define A_HI 0
#define A_LO 16384
#define C_HI 32768
#define C_LO 49152
#define U_HI 65536
#define U_LO 81920
#define P_HI 98304
#define P_LO 106496
#define SMEM_TOTAL 114688

// partial sums: [b*S_CHUNKS+chunk][q*DN+d]  (33.5 MB)
__device__ float g_part[(size_t)B_ * S_CHUNKS * QN * DN];

__device__ __forceinline__ uint32_t smem_u32(const void* p) {
    uint32_t a;
    asm("{ .reg .u64 t; cvta.to.shared.u64 t, %1; cvt.u32.u64 %0, t; }" : "=r"(a) : "l"(p));
    return a;
}
// swizzled byte offset within a 256B-row tile: row r, 16B-granule g
__device__ __forceinline__ uint32_t swz(uint32_t r, uint32_t g) {
    return r * ROW + ((g ^ (r & 7)) << 4);
}
__device__ __forceinline__ uint32_t swzp(uint32_t r, uint32_t g) {  // P: 128B rows
    return r * PROW + ((g ^ (r & 7)) << 4);
}
__device__ __forceinline__ void ldsm4(uint32_t* r, uint32_t a) {
    asm volatile("ldmatrix.sync.aligned.m8n8.x4.shared.b16 {%0,%1,%2,%3}, [%4];"
                 : "=r"(r[0]), "=r"(r[1]), "=r"(r[2]), "=r"(r[3]) : "r"(a));
}
__device__ __forceinline__ void ldsm4t(uint32_t* r, uint32_t a) {
    asm volatile("ldmatrix.sync.aligned.m8n8.x4.trans.shared.b16 {%0,%1,%2,%3}, [%4];"
                 : "=r"(r[0]), "=r"(r[1]), "=r"(r[2]), "=r"(r[3]) : "r"(a));
}
__device__ __forceinline__ void mma_bf16(float* d, const uint32_t* a, const uint32_t* b) {
    asm volatile(
        "mma.sync.aligned.m16n8k16.row.col.f32.bf16.bf16.f32 "
        "{%0,%1,%2,%3}, {%4,%5,%6,%7}, {%8,%9}, {%0,%1,%2,%3};"
        : "+f"(d[0]), "+f"(d[1]), "+f"(d[2]), "+f"(d[3])
        : "r"(a[0]), "r"(a[1]), "r"(a[2]), "r"(a[3]), "r"(b[0]), "r"(b[1]));
}
__device__ __forceinline__ void cvt2(float x0, float x1, uint32_t& hi, uint32_t& lo) {
    __nv_bfloat162 h = __float22bfloat162_rn(make_float2(x0, x1));
    hi = *reinterpret_cast<uint32_t*>(&h);
    float h0 = __uint_as_float(hi << 16);
    float h1 = __uint_as_float(hi & 0xFFFF0000u);
    __nv_bfloat162 l = __float22bfloat162_rn(make_float2(x0 - h0, x1 - h1));
    lo = *reinterpret_cast<uint32_t*>(&l);
}

// ---------------------------------------------------------------------------
// out[b,q,:] = u[b,q,:] @ H    (4 q-rows per block for H L2-traffic reuse)
// ---------------------------------------------------------------------------
__global__ __launch_bounds__(128) void uh_kernel(
    const float* __restrict__ u, const float* __restrict__ H, float* __restrict__ out)
{
    __shared__ float us[4][DN];
    const int b4 = blockIdx.x, tid = threadIdx.x;
#pragma unroll
    for (int r = 0; r < 4; ++r)
        us[r][tid] = u[((size_t)b4 * 4 + r) * DN + tid];
    __syncthreads();
    float acc[4] = {0.f, 0.f, 0.f, 0.f};
#pragma unroll 8
    for (int e = 0; e < DN; ++e) {
        float h = H[e * DN + tid];
#pragma unroll
        for (int r = 0; r < 4; ++r) acc[r] += us[r][e] * h;
    }
#pragma unroll
    for (int r = 0; r < 4; ++r)
        out[((size_t)b4 * 4 + r) * DN + tid] = acc[r];
}

// ---------------------------------------------------------------------------
__global__ __launch_bounds__(THREADS, 2) void attn_mma(
    const float* __restrict__ story_a, const float* __restrict__ u,
    const float* __restrict__ story_c)
{
    extern __shared__ char sm[];
    const uint32_t sb = smem_u32(sm);
    const int tid = threadIdx.x, lane = tid & 31, wid = tid >> 5;
    const int b = blockIdx.y, chunk = blockIdx.x;
    const int m_base_g = chunk * CHUNK;

    // ---- stage u (64q x 128d), hi/lo, swizzled ----
    {
        const float4* g4 = reinterpret_cast<const float4*>(u + (size_t)b * QN * DN);
        for (int i = tid; i < QN * DN / 4; i += THREADS) {
            int q = i >> 5, j = i & 31;
            float4 v = g4[i];
            uint32_t h0, l0, h1, l1;
            cvt2(v.x, v.y, h0, l0); cvt2(v.z, v.w, h1, l1);
            uint32_t off = swz(q, j >> 1) + (j & 1) * 8;
            *reinterpret_cast<uint2*>(sm + U_HI + off) = make_uint2(h0, h1);
            *reinterpret_cast<uint2*>(sm + U_LO + off) = make_uint2(l0, l1);
        }
    }

    // GEMM1: warp = 16m x 64q.  A row-major frag, U col-major frag.
    const uint32_t a1_row = (uint32_t)(wid * 16 + (lane & 15));
    const uint32_t a1_gh  = (lane & 16) ? 1u : 0u;
    const uint32_t b1_row = (uint32_t)((lane & 7) + ((lane & 16) ? 8 : 0));
    const uint32_t b1_gh  = (lane & 8) ? 1u : 0u;
    // GEMM2: warp = 16q x 128d.  P^T via trans-ldsm, C^T via trans-ldsm.
    const uint32_t pa_row = (uint32_t)((lane & 7) + ((lane & 16) ? 8 : 0));
    const uint32_t pa_g   = (uint32_t)(wid * 2 + ((lane & 8) ? 1 : 0));
    const uint32_t cb_row = (uint32_t)((lane & 7) + ((lane & 8) ? 8 : 0));
    const uint32_t cb_gh  = (lane & 16) ? 1u : 0u;

    float cacc[16][4];
#pragma unroll
    for (int i = 0; i < 16; ++i)
#pragma unroll
        for (int j = 0; j < 4; ++j) cacc[i][j] = 0.f;

    for (int t = 0; t < NT; ++t) {
        __syncthreads();   // previous tile's GEMM2 done with C/P

        // ---- stage story_a & story_c tiles (64m x 128d), hi/lo ----
        {
            const float4* ga = reinterpret_cast<const float4*>(
                story_a + ((size_t)b * M_ + m_base_g + t * MT) * DN);
            const float4* gc = reinterpret_cast<const float4*>(
                story_c + ((size_t)b * M_ + m_base_g + t * MT) * DN);
            for (int i = tid; i < MT * DN / 4; i += THREADS) {
                int m = i >> 5, j = i & 31;
                uint32_t off = swz(m, j >> 1) + (j & 1) * 8;
                float4 v = ga[i];
                uint32_t h0, l0, h1, l1;
                cvt2(v.x, v.y, h0, l0); cvt2(v.z, v.w, h1, l1);
                *reinterpret_cast<uint2*>(sm + A_HI + off) = make_uint2(h0, h1);
                *reinterpret_cast<uint2*>(sm + A_LO + off) = make_uint2(l0, l1);
                v = gc[i];
                cvt2(v.x, v.y, h0, l0); cvt2(v.z, v.w, h1, l1);
                *reinterpret_cast<uint2*>(sm + C_HI + off) = make_uint2(h0, h1);
                *reinterpret_cast<uint2*>(sm + C_LO + off) = make_uint2(l0, l1);
            }
        }
        __syncthreads();

        // ---- GEMM1: S[16m][64q], 3-pass hi/lo, K = d = 128 ----
        float s[8][4];
#pragma unroll
        for (int i = 0; i < 8; ++i)
#pragma unroll
            for (int j = 0; j < 4; ++j) s[i][j] = 0.f;

#pragma unroll
        for (int ks = 0; ks < 8; ++ks) {
            uint32_t ah[4], al[4];
            uint32_t aaddr = sb + A_HI + swz(a1_row, (uint32_t)ks * 2 + a1_gh);
            ldsm4(ah, aaddr);
            ldsm4(al, aaddr + (A_LO - A_HI));
#pragma unroll
            for (int ntp = 0; ntp < 4; ++ntp) {
                uint32_t bh[4], bl[4];
                uint32_t baddr = sb + U_HI
                    + swz((uint32_t)(ntp * 16) + b1_row, (uint32_t)ks * 2 + b1_gh);
                ldsm4(bh, baddr);
                ldsm4(bl, baddr + (U_LO - U_HI));
#pragma unroll
                for (int j = 0; j < 2; ++j) {
                    mma_bf16(s[ntp * 2 + j], ah, bh + 2 * j);
                    mma_bf16(s[ntp * 2 + j], ah, bl + 2 * j);
                    mma_bf16(s[ntp * 2 + j], al, bh + 2 * j);
                }
            }
        }

        // ---- softmax over q (warp-local rows r1, r2 = r1+8) ----
        {
            float mx1 = -1e30f, mx2 = -1e30f;
#pragma unroll
            for (int nt = 0; nt < 8; ++nt) {
                mx1 = fmaxf(mx1, fmaxf(s[nt][0], s[nt][1]));
                mx2 = fmaxf(mx2, fmaxf(s[nt][2], s[nt][3]));
            }
            mx1 = fmaxf(mx1, __shfl_xor_sync(0xffffffffu, mx1, 1));
            mx1 = fmaxf(mx1, __shfl_xor_sync(0xffffffffu, mx1, 2));
            mx2 = fmaxf(mx2, __shfl_xor_sync(0xffffffffu, mx2, 1));
            mx2 = fmaxf(mx2, __shfl_xor_sync(0xffffffffu, mx2, 2));
            float sum1 = 0.f, sum2 = 0.f;
#pragma unroll
            for (int nt = 0; nt < 8; ++nt) {
                s[nt][0] = __expf(s[nt][0] - mx1); sum1 += s[nt][0];
                s[nt][1] = __expf(s[nt][1] - mx1); sum1 += s[nt][1];
                s[nt][2] = __expf(s[nt][2] - mx2); sum2 += s[nt][2];
                s[nt][3] = __expf(s[nt][3] - mx2); sum2 += s[nt][3];
            }
            sum1 += __shfl_xor_sync(0xffffffffu, sum1, 1);
            sum1 += __shfl_xor_sync(0xffffffffu, sum1, 2);
            sum2 += __shfl_xor_sync(0xffffffffu, sum2, 1);
            sum2 += __shfl_xor_sync(0xffffffffu, sum2, 2);
            float inv1 = 1.f / sum1, inv2 = 1.f / sum2;

            const uint32_t r1 = (uint32_t)(wid * 16 + (lane >> 2)), r2 = r1 + 8;
            const uint32_t qb = (uint32_t)(lane & 3) * 4;
#pragma unroll
            for (int nt = 0; nt < 8; ++nt) {
                uint32_t h, l;
                uint32_t o1 = swzp(r1, (uint32_t)nt) + qb;
                uint32_t o2 = swzp(r2, (uint32_t)nt) + qb;
                cvt2(s[nt][0] * inv1, s[nt][1] * inv1, h, l);
                *reinterpret_cast<uint32_t*>(sm + P_HI + o1) = h;
                *reinterpret_cast<uint32_t*>(sm + P_LO + o1) = l;
                cvt2(s[nt][2] * inv2, s[nt][3] * inv2, h, l);
                *reinterpret_cast<uint32_t*>(sm + P_HI + o2) = h;
                *reinterpret_cast<uint32_t*>(sm + P_LO + o2) = l;
            }
        }
        __syncthreads();

        // ---- GEMM2: C[16q][128d] += P^T * SC, K = m = 64 ----
#pragma unroll
        for (int ks = 0; ks < 4; ++ks) {
            uint32_t ph[4], pl[4];
            uint32_t paddr = sb + P_HI + swzp((uint32_t)ks * 16 + pa_row, pa_g);
            ldsm4t(ph, paddr);
            ldsm4t(pl, paddr + (P_LO - P_HI));
#pragma unroll
            for (int ntp = 0; ntp < 8; ++ntp) {
                uint32_t bh[4], bl[4];
                uint32_t baddr = sb + C_HI
                    + swz((uint32_t)ks * 16 + cb_row, (uint32_t)ntp * 2 + cb_gh);
                ldsm4t(bh, baddr);
                ldsm4t(bl, baddr + (C_LO - C_HI));
#pragma unroll
                for (int j = 0; j < 2; ++j) {
                    mma_bf16(cacc[ntp * 2 + j], ph, bh + 2 * j);
                    mma_bf16(cacc[ntp * 2 + j], ph, bl + 2 * j);
                    mma_bf16(cacc[ntp * 2 + j], pl, bh + 2 * j);
                }
            }
        }
    }

    // ---- write partials ----
    {
        float* part = g_part + (size_t)(b * S_CHUNKS + chunk) * (QN * DN);
        const int q1 = wid * 16 + (lane >> 2), q2 = q1 + 8;
#pragma unroll
        for (int nt = 0; nt < 16; ++nt) {
            int d0 = (nt >> 1) * 16 + (nt & 1) * 8 + (lane & 3) * 2;
            *reinterpret_cast<float2*>(part + q1 * DN + d0) =
                make_float2(cacc[nt][0], cacc[nt][1]);
            *reinterpret_cast<float2*>(part + q2 * DN + d0) =
                make_float2(cacc[nt][2], cacc[nt][3]);
        }
    }
}

// ---------------------------------------------------------------------------
__global__ __launch_bounds__(256) void reduce_kernel(float* __restrict__ out)
{
    int i = blockIdx.x * 256 + threadIdx.x;   // 0 .. B*Q*D-1
    int b = i >> 13;                          // Q*D = 8192
    int qd = i & 8191;
    float v = 0.f;
#pragma unroll
    for (int ch = 0; ch < S_CHUNKS; ++ch)
        v += g_part[(size_t)(b * S_CHUNKS + ch) * (QN * DN) + qd];
    out[i] += v;
}

// ---------------------------------------------------------------------------
extern "C" void kernel_launch(void* const* d_in, const int* in_sizes, int n_in,
                              void* d_out, int out_size)
{
    (void)in_sizes; (void)n_in; (void)out_size;
    const float* story_a = (const float*)d_in[0];
    const float* u       = (const float*)d_in[1];
    const float* story_c = (const float*)d_in[2];
    const float* H       = (const float*)d_in[3];
    float* out = (float*)d_out;

    uh_kernel<<<B_ * QN / 4, 128>>>(u, H, out);

    cudaFuncSetAttribute(attn_mma, cudaFuncAttributeMaxDynamicSharedMemorySize, SMEM_TOTAL);
    dim3 grid(S_CHUNKS, B_);
    attn_mma<<<grid, THREADS, SMEM_TOTAL>>>(story_a, u, story_c);

    reduce_kernel<<<(B_ * QN * DN) / 256, 256>>>(out);
}